// round 5
// baseline (speedup 1.0000x reference)
#include <cuda_runtime.h>
#include <cuda_fp16.h>
#include <cstdint>

#define Bn 8192
#define Dn 2048
#define Cn 751
#define CnP 768
#define NCAMS 16
#define MARGINF 0.3f
#define IT (1.0f/0.07f)
#define L2E 1.44269504f
#define LN2f 0.69314718f
#define CEXP (IT*L2E)
#define BIGF 1.0e9f
#define L_TRI 0.5f
#define L_ST 0.3f
#define WSCALE 16.0f
#define WINV (1.0f/16.0f)

// tiling (byte-based K: fp8 = 1 byte/elem)
#define BM 128
#define BN 256
#define BKB 64                   // K bytes per stage (= 64 fp8 elements)
#define KTp (Dn/BKB)             // 32 k-steps per column tile
#define CTp 4                    // column tiles per CTA
#define COLS_PER (BN*CTp)        // 1024
#define NSPLIT (Bn/COLS_PER)     // 8
#define JMAXp (CTp*KTp)          // 128
#define STG 24576                // stage bytes: A 8KB + B 16KB
#define SM_REACH (4*STG)
#define SM_SQ  (SM_REACH+1024)
#define SM_INV (SM_SQ+1024)
#define SM_TS  (SM_INV+1024)
#define SM_LAB (SM_TS+1024)
#define SM_CAM (SM_LAB+1024)
#define SMEM_PAIR (SM_CAM+1024)  // 104448
#define SMEM_CLS (4*STG+1024)

// swizzled smem offset: 64B rows, 16B chunks, perm = c ^ ((row>>1)&3)
#define SW(row, ch) ((row)*64 + ((((ch) ^ (((row)>>1)&3)))<<4))

// ---------------- device scratch ----------------
__device__ uint8_t g_F8[(size_t)Bn*Dn];    // 16 MB, e4m3
__device__ uint8_t g_W8[(size_t)CnP*Dn];   // 1.5 MB, e4m3 of 16*W (rows>=Cn zero)
__device__ float    g_sq[Bn], g_invn[Bn];
__device__ float    g_sume[Bn], g_spos[Bn], g_cpos[Bn];
__device__ unsigned g_hp[Bn], g_hn[Bn];
__device__ float    g_sume_cls[Bn], g_lab_logit[Bn];
__device__ float    g_acc[8];

__device__ __forceinline__ unsigned f2o(float f){
    unsigned u = __float_as_uint(f);
    return (u & 0x80000000u) ? ~u : (u | 0x80000000u);
}
__device__ __forceinline__ float o2f(unsigned u){
    return __uint_as_float((u & 0x80000000u) ? (u & 0x7fffffffu) : ~u);
}

__device__ __forceinline__ uint32_t pack_e4m3_4(float x0, float x1, float x2, float x3){
    uint16_t lo, hi;
    asm("cvt.rn.satfinite.e4m3x2.f32 %0, %1, %2;" : "=h"(lo) : "f"(x1), "f"(x0));
    asm("cvt.rn.satfinite.e4m3x2.f32 %0, %1, %2;" : "=h"(hi) : "f"(x3), "f"(x2));
    return (uint32_t)lo | ((uint32_t)hi << 16);
}
__device__ __forceinline__ float sq_e4m3x2(uint16_t h){
    uint32_t f2;
    asm("cvt.rn.f16x2.e4m3x2 %0, %1;" : "=r"(f2) : "h"(h));
    __half2 hh = *reinterpret_cast<__half2*>(&f2);
    float2 f = __half22float2(hh);
    return f.x*f.x + f.y*f.y;
}
__device__ __forceinline__ float sq_u32(uint32_t u){
    return sq_e4m3x2((uint16_t)(u & 0xFFFF)) + sq_e4m3x2((uint16_t)(u >> 16));
}

#define CP16(dst, src) asm volatile("cp.async.cg.shared.global [%0], [%1], 16;" :: "r"(dst), "l"(src) : "memory")
#define CP_COMMIT()    asm volatile("cp.async.commit_group;" ::: "memory")
#define CP_WAIT(n)     asm volatile("cp.async.wait_group %0;" :: "n"(n) : "memory")

__device__ __forceinline__ void ldm4(uint32_t &r0, uint32_t &r1, uint32_t &r2, uint32_t &r3, uint32_t addr){
    asm volatile("ldmatrix.sync.aligned.m8n8.x4.shared.b16 {%0,%1,%2,%3}, [%4];"
        : "=r"(r0), "=r"(r1), "=r"(r2), "=r"(r3) : "r"(addr));
}
__device__ __forceinline__ void mma_fp8(float* d, const uint32_t* a, const uint32_t* b){
    asm volatile("mma.sync.aligned.m16n8k32.row.col.f32.e4m3.e4m3.f32 "
        "{%0,%1,%2,%3}, {%4,%5,%6,%7}, {%8,%9}, {%0,%1,%2,%3};"
        : "+f"(d[0]), "+f"(d[1]), "+f"(d[2]), "+f"(d[3])
        : "r"(a[0]), "r"(a[1]), "r"(a[2]), "r"(a[3]), "r"(b[0]), "r"(b[1]));
}

// ---------------- conversion / init / norms ----------------
__global__ void convert_F_kernel(const float* __restrict__ F){
    size_t i = ((size_t)blockIdx.x*blockDim.x + threadIdx.x)*16;
    float4 v0 = *(const float4*)(F+i);
    float4 v1 = *(const float4*)(F+i+4);
    float4 v2 = *(const float4*)(F+i+8);
    float4 v3 = *(const float4*)(F+i+12);
    uint4 o;
    o.x = pack_e4m3_4(v0.x,v0.y,v0.z,v0.w);
    o.y = pack_e4m3_4(v1.x,v1.y,v1.z,v1.w);
    o.z = pack_e4m3_4(v2.x,v2.y,v2.z,v2.w);
    o.w = pack_e4m3_4(v3.x,v3.y,v3.z,v3.w);
    *(uint4*)(g_F8 + i) = o;
}
__global__ void convert_W_kernel(const float* __restrict__ W){
    size_t i = ((size_t)blockIdx.x*blockDim.x + threadIdx.x)*16;
    size_t row = i / Dn;
    uint4 o;
    if (row < Cn){
        float4 v0 = *(const float4*)(W+i);
        float4 v1 = *(const float4*)(W+i+4);
        float4 v2 = *(const float4*)(W+i+8);
        float4 v3 = *(const float4*)(W+i+12);
        o.x = pack_e4m3_4(v0.x*WSCALE,v0.y*WSCALE,v0.z*WSCALE,v0.w*WSCALE);
        o.y = pack_e4m3_4(v1.x*WSCALE,v1.y*WSCALE,v1.z*WSCALE,v1.w*WSCALE);
        o.z = pack_e4m3_4(v2.x*WSCALE,v2.y*WSCALE,v2.z*WSCALE,v2.w*WSCALE);
        o.w = pack_e4m3_4(v3.x*WSCALE,v3.y*WSCALE,v3.z*WSCALE,v3.w*WSCALE);
    } else { o.x=o.y=o.z=o.w=0u; }
    *(uint4*)(g_W8 + i) = o;
}
__global__ void init_kernel(){
    int i = blockIdx.x*blockDim.x + threadIdx.x;
    if (i < Bn){
        g_sume[i]=0.f; g_spos[i]=0.f; g_cpos[i]=0.f;
        g_hp[i]=f2o(-BIGF); g_hn[i]=f2o(BIGF);
        g_sume_cls[i]=0.f; g_lab_logit[i]=0.f;
    }
    if (i < 8) g_acc[i]=0.f;
}
__global__ void norm_kernel(){
    int row  = blockIdx.x*(blockDim.x>>5) + (threadIdx.x>>5);
    int lane = threadIdx.x & 31;
    const uint4* p = (const uint4*)(g_F8 + (size_t)row*Dn);
    float s = 0.f;
    #pragma unroll
    for (int i = lane; i < Dn/16; i += 32){
        uint4 v = p[i];
        s += sq_u32(v.x) + sq_u32(v.y) + sq_u32(v.z) + sq_u32(v.w);
    }
    #pragma unroll
    for (int o=16;o;o>>=1) s += __shfl_xor_sync(0xffffffffu, s, o);
    if (lane==0){ g_sq[row]=s; g_invn[row]=rsqrtf(s); }
}

// ---------------- fused Gram kernel (fp8 mma.sync, cp.async 4-stage) ----------------
__global__ __launch_bounds__(512) void pair_kernel(
    const int* __restrict__ lab, const int* __restrict__ cam,
    const float* __restrict__ ts, const float* __restrict__ reach)
{
    extern __shared__ char smem[];
    uint32_t sb = (uint32_t)__cvta_generic_to_shared(smem);
    int tid = threadIdx.x, lane = tid&31, wid = tid>>5;
    int wm = wid&3, wn = wid>>2;
    int row0 = blockIdx.x*BM;
    int colstart = blockIdx.y*COLS_PER;

    float* s_reach=(float*)(smem+SM_REACH);
    float* s_sq  =(float*)(smem+SM_SQ);
    float* s_invn=(float*)(smem+SM_INV);
    float* s_ts  =(float*)(smem+SM_TS);
    int*   s_lab =(int*)  (smem+SM_LAB);
    int*   s_cam =(int*)  (smem+SM_CAM);
    if (tid < 256) s_reach[tid] = reach[tid];

    // loader mapping: A = 512 16B-chunks (1/thread), B = 1024 (2/thread)
    int rA = tid>>2, cA = tid&3;
    uint32_t dA = SW(rA, cA);
    const uint8_t* gA = g_F8 + (size_t)(row0+rA)*Dn + cA*16;
    int rB1 = (tid+512)>>2;
    uint32_t dB0 = 8192 + SW(rA, cA);
    uint32_t dB1 = 8192 + SW(rB1, cA);
    const uint8_t* gB0 = g_F8 + (size_t)(colstart+rA)*Dn + cA*16;
    const uint8_t* gB1 = g_F8 + (size_t)(colstart+rB1)*Dn + cA*16;

    // ldmatrix per-lane offsets (identical structure to bf16 version; 16B chunks)
    int q = lane>>3, rr = lane&7;
    int offA_ld[2][2], offB_ld[4][2];
    #pragma unroll
    for (int mt=0; mt<2; mt++)
        #pragma unroll
        for (int ks=0; ks<2; ks++){
            int row = wm*32 + mt*16 + rr + (q&1)*8;
            offA_ld[mt][ks] = SW(row, ks*2 + (q>>1));
        }
    #pragma unroll
    for (int nt4=0; nt4<4; nt4++)
        #pragma unroll
        for (int ks=0; ks<2; ks++){
            int row = wn*64 + nt4*16 + rr + (q>>1)*8;
            offB_ld[nt4][ks] = 8192 + SW(row, ks*2 + (q&1));
        }

    float acc[2][8][4];
    #pragma unroll
    for (int i=0;i<2;i++)
        #pragma unroll
        for (int j=0;j<8;j++)
            #pragma unroll
            for (int e=0;e<4;e++) acc[i][j][e]=0.f;
    float sume4[4], spos4[4], cpos4[4], hp4[4], hn4[4];
    #pragma unroll
    for (int x=0;x<4;x++){ sume4[x]=0.f; spos4[x]=0.f; cpos4[x]=0.f; hp4[x]=-BIGF; hn4[x]=BIGF; }

    #define PLOAD(j) do { \
        int _ct=(j)>>5, _kt=(j)&31; \
        uint32_t _st = sb + ((j)&3)*STG; \
        size_t _ko = (size_t)_kt*BKB; \
        size_t _co = (size_t)_ct*((size_t)BN*Dn); \
        CP16(_st+dA,  gA  + _ko); \
        CP16(_st+dB0, gB0 + _co + _ko); \
        CP16(_st+dB1, gB1 + _co + _ko); \
    } while(0)

    PLOAD(0); CP_COMMIT();
    PLOAD(1); CP_COMMIT();
    PLOAD(2); CP_COMMIT();

    for (int j=0; j<JMAXp; j++){
        CP_WAIT(2);
        __syncthreads();
        if ((j&31)==0 && tid<256){           // column metadata for this ct
            int cj = colstart + (j>>5)*BN + tid;
            s_sq[tid]=g_sq[cj]; s_invn[tid]=g_invn[cj]; s_ts[tid]=ts[cj];
            s_lab[tid]=lab[cj]; s_cam[tid]=cam[cj];
        }
        if (j+3 < JMAXp) PLOAD(j+3);
        CP_COMMIT();

        uint32_t st = sb + (j&3)*STG;
        #pragma unroll
        for (int ks=0; ks<2; ks++){
            uint32_t a[2][4], b[8][2];
            ldm4(a[0][0],a[0][1],a[0][2],a[0][3], st + offA_ld[0][ks]);
            ldm4(a[1][0],a[1][1],a[1][2],a[1][3], st + offA_ld[1][ks]);
            #pragma unroll
            for (int nt4=0; nt4<4; nt4++)
                ldm4(b[nt4*2][0],b[nt4*2][1],b[nt4*2+1][0],b[nt4*2+1][1], st + offB_ld[nt4][ks]);
            #pragma unroll
            for (int mt=0; mt<2; mt++)
                #pragma unroll
                for (int nt=0; nt<8; nt++)
                    mma_fp8(acc[mt][nt], a[mt], b[nt]);
        }

        if ((j&31)==31){
            int col0 = colstart + (j>>5)*BN;
            #pragma unroll
            for (int mt=0; mt<2; mt++)
                #pragma unroll
                for (int h=0; h<2; h++){
                    int x = mt*2 + h;
                    int ri = row0 + wm*32 + mt*16 + h*8 + (lane>>2);
                    float sqi = g_sq[ri], ari = g_invn[ri]*CEXP, tsi = ts[ri];
                    int labi = lab[ri], cami = cam[ri]*NCAMS;
                    #pragma unroll
                    for (int nt=0; nt<8; nt++){
                        int cl = wn*64 + nt*8 + (lane&3)*2;
                        #pragma unroll
                        for (int u=0; u<2; u++){
                            int clu = cl+u, cj = col0+clu;
                            float g  = acc[mt][nt][h*2+u];
                            float d2 = fmaxf(fmaf(-2.f, g, sqi + s_sq[clu]), 0.f);
                            bool eye  = (ri == cj);
                            bool same = (labi == s_lab[clu]);
                            if (same && !eye) hp4[x] = fmaxf(hp4[x], d2);
                            else              hn4[x] = fminf(hn4[x], d2);
                            float tt = fmaf(g*ari, s_invn[clu], -CEXP);
                            float ev; asm("ex2.approx.ftz.f32 %0, %1;" : "=f"(ev) : "f"(tt));
                            sume4[x] += ev;
                            float dt = fabsf(tsi - s_ts[clu]);
                            if (same && !eye && dt <= s_reach[cami + s_cam[clu]]){
                                spos4[x] += fmaf(tt, LN2f, IT); cpos4[x] += 1.f;
                            }
                        }
                    }
                }
            #pragma unroll
            for (int i=0;i<2;i++)
                #pragma unroll
                for (int t=0;t<8;t++)
                    #pragma unroll
                    for (int e=0;e<4;e++) acc[i][t][e]=0.f;
        }
    }

    #pragma unroll
    for (int o=1;o<=2;o<<=1){
        #pragma unroll
        for (int x=0;x<4;x++){
            sume4[x] += __shfl_xor_sync(0xffffffffu, sume4[x], o);
            spos4[x] += __shfl_xor_sync(0xffffffffu, spos4[x], o);
            cpos4[x] += __shfl_xor_sync(0xffffffffu, cpos4[x], o);
            hp4[x] = fmaxf(hp4[x], __shfl_xor_sync(0xffffffffu, hp4[x], o));
            hn4[x] = fminf(hn4[x], __shfl_xor_sync(0xffffffffu, hn4[x], o));
        }
    }
    if ((lane&3)==0){
        #pragma unroll
        for (int x=0;x<4;x++){
            int ri = row0 + wm*32 + (x>>1)*16 + (x&1)*8 + (lane>>2);
            atomicAdd(&g_sume[ri], sume4[x]);
            atomicAdd(&g_spos[ri], spos4[x]);
            atomicAdd(&g_cpos[ri], cpos4[x]);
            atomicMax(&g_hp[ri], f2o(hp4[x]));
            atomicMin(&g_hn[ri], f2o(hn4[x]));
        }
    }
    #undef PLOAD
}

// ---------------- classifier (fp8 mma.sync) ----------------
__global__ __launch_bounds__(512) void cls_kernel(
    const float* __restrict__ bbias, const int* __restrict__ lab)
{
    extern __shared__ char smem[];
    uint32_t sb = (uint32_t)__cvta_generic_to_shared(smem);
    int tid = threadIdx.x, lane = tid&31, wid = tid>>5;
    int wm = wid&3, wn = wid>>2;
    int row0 = blockIdx.x*BM;
    int col0 = blockIdx.y*BN;
    float* s_b = (float*)(smem + 4*STG);
    if (tid < 256){
        int cj = col0 + tid;
        s_b[tid] = (cj < Cn) ? bbias[cj] : 0.f;
    }

    int rA = tid>>2, cA = tid&3;
    uint32_t dA = SW(rA, cA);
    const uint8_t* gA = g_F8 + (size_t)(row0+rA)*Dn + cA*16;
    int rB1 = (tid+512)>>2;
    uint32_t dB0 = 8192 + SW(rA, cA);
    uint32_t dB1 = 8192 + SW(rB1, cA);
    const uint8_t* gB0 = g_W8 + (size_t)(col0+rA)*Dn + cA*16;
    const uint8_t* gB1 = g_W8 + (size_t)(col0+rB1)*Dn + cA*16;

    int q = lane>>3, rr = lane&7;
    int offA_ld[2][2], offB_ld[4][2];
    #pragma unroll
    for (int mt=0; mt<2; mt++)
        #pragma unroll
        for (int ks=0; ks<2; ks++){
            int row = wm*32 + mt*16 + rr + (q&1)*8;
            offA_ld[mt][ks] = SW(row, ks*2 + (q>>1));
        }
    #pragma unroll
    for (int nt4=0; nt4<4; nt4++)
        #pragma unroll
        for (int ks=0; ks<2; ks++){
            int row = wn*64 + nt4*16 + rr + (q>>1)*8;
            offB_ld[nt4][ks] = 8192 + SW(row, ks*2 + (q&1));
        }

    float acc[2][8][4];
    #pragma unroll
    for (int i=0;i<2;i++)
        #pragma unroll
        for (int j=0;j<8;j++)
            #pragma unroll
            for (int e=0;e<4;e++) acc[i][j][e]=0.f;

    #define CLOAD(j) do { \
        uint32_t _st = sb + ((j)&3)*STG; \
        size_t _ko = (size_t)(j)*BKB; \
        CP16(_st+dA,  gA  + _ko); \
        CP16(_st+dB0, gB0 + _ko); \
        CP16(_st+dB1, gB1 + _ko); \
    } while(0)

    CLOAD(0); CP_COMMIT();
    CLOAD(1); CP_COMMIT();
    CLOAD(2); CP_COMMIT();

    for (int j=0; j<KTp; j++){
        CP_WAIT(2);
        __syncthreads();
        if (j+3 < KTp) CLOAD(j+3);
        CP_COMMIT();
        uint32_t st = sb + (j&3)*STG;
        #pragma unroll
        for (int ks=0; ks<2; ks++){
            uint32_t a[2][4], b[8][2];
            ldm4(a[0][0],a[0][1],a[0][2],a[0][3], st + offA_ld[0][ks]);
            ldm4(a[1][0],a[1][1],a[1][2],a[1][3], st + offA_ld[1][ks]);
            #pragma unroll
            for (int nt4=0; nt4<4; nt4++)
                ldm4(b[nt4*2][0],b[nt4*2][1],b[nt4*2+1][0],b[nt4*2+1][1], st + offB_ld[nt4][ks]);
            #pragma unroll
            for (int mt=0; mt<2; mt++)
                #pragma unroll
                for (int nt=0; nt<8; nt++)
                    mma_fp8(acc[mt][nt], a[mt], b[nt]);
        }
    }

    float se4[4];
    #pragma unroll
    for (int x=0;x<4;x++) se4[x]=0.f;
    #pragma unroll
    for (int mt=0; mt<2; mt++)
        #pragma unroll
        for (int h=0; h<2; h++){
            int x = mt*2 + h;
            int ri = row0 + wm*32 + mt*16 + h*8 + (lane>>2);
            int labi = lab[ri];
            #pragma unroll
            for (int nt=0; nt<8; nt++){
                int cl = wn*64 + nt*8 + (lane&3)*2;
                #pragma unroll
                for (int u=0; u<2; u++){
                    int clu = cl+u, cj = col0+clu;
                    float logit = fmaf(acc[mt][nt][h*2+u], WINV, s_b[clu]);
                    if (cj < Cn){
                        se4[x] += __expf(logit);
                        if (cj == labi) g_lab_logit[ri] = logit;
                    }
                }
            }
        }
    #pragma unroll
    for (int o=1;o<=2;o<<=1)
        #pragma unroll
        for (int x=0;x<4;x++)
            se4[x] += __shfl_xor_sync(0xffffffffu, se4[x], o);
    if ((lane&3)==0){
        #pragma unroll
        for (int x=0;x<4;x++){
            int ri = row0 + wm*32 + (x>>1)*16 + (x&1)*8 + (lane>>2);
            atomicAdd(&g_sume_cls[ri], se4[x]);
        }
    }
    #undef CLOAD
}

// ---------------- final reductions ----------------
__global__ void fin1(){
    int i = blockIdx.x*blockDim.x + threadIdx.x;
    float tri=0.f, nv=0.f, stn=0.f, stc=0.f, cls=0.f;
    if (i < Bn){
        float lse = IT + logf(g_sume[i]);
        stn = g_spos[i] - g_cpos[i]*lse;
        stc = g_cpos[i];
        float hp = o2f(g_hp[i]), hn = o2f(g_hn[i]);
        bool valid = hp > -1.0e8f;
        tri = valid ? fmaxf(hp - hn + MARGINF, 0.f) : 0.f;
        nv  = valid ? 1.f : 0.f;
        cls = logf(g_sume_cls[i]) - g_lab_logit[i];
    }
    #pragma unroll
    for (int o=16;o;o>>=1){
        tri += __shfl_down_sync(0xffffffffu, tri, o);
        nv  += __shfl_down_sync(0xffffffffu, nv , o);
        stn += __shfl_down_sync(0xffffffffu, stn, o);
        stc += __shfl_down_sync(0xffffffffu, stc, o);
        cls += __shfl_down_sync(0xffffffffu, cls, o);
    }
    if ((threadIdx.x & 31) == 0){
        atomicAdd(&g_acc[0], tri);
        atomicAdd(&g_acc[1], nv);
        atomicAdd(&g_acc[2], stn);
        atomicAdd(&g_acc[3], stc);
        atomicAdd(&g_acc[4], cls);
    }
}
__global__ void fin2(float* out){
    float nv = g_acc[1], npos = g_acc[3];
    float loss_id  = g_acc[4] / (float)Bn;
    float loss_tri = (nv   > 0.f) ? g_acc[0] / fmaxf(nv,   1.f) : 0.f;
    float loss_st  = (npos > 0.f) ? (-g_acc[2]) / fmaxf(npos, 1.f) : 0.f;
    out[0] = loss_id + L_TRI*loss_tri + L_ST*loss_st;
}

// ---------------- launch ----------------
extern "C" void kernel_launch(void* const* d_in, const int* in_sizes, int n_in,
                              void* d_out, int out_size){
    const float* F     = (const float*)d_in[0];
    const int*   lab   = (const int*)  d_in[1];
    const int*   cam   = (const int*)  d_in[2];
    const float* ts    = (const float*)d_in[3];
    const float* reach = (const float*)d_in[4];
    const float* W     = (const float*)d_in[5];
    const float* bbias = (const float*)d_in[6];
    float* out = (float*)d_out;

    cudaFuncSetAttribute(pair_kernel, cudaFuncAttributeMaxDynamicSharedMemorySize, SMEM_PAIR);
    cudaFuncSetAttribute(cls_kernel,  cudaFuncAttributeMaxDynamicSharedMemorySize, SMEM_CLS);

    convert_F_kernel<<<(Bn*(size_t)Dn/16)/256, 256>>>(F);
    convert_W_kernel<<<((size_t)CnP*Dn/16)/256, 256>>>(W);
    init_kernel<<<(Bn+255)/256, 256>>>();
    norm_kernel<<<Bn/8, 256>>>();
    dim3 g1(Bn/BM, NSPLIT);
    pair_kernel<<<g1, 512, SMEM_PAIR>>>(lab, cam, ts, reach);
    dim3 g2(Bn/BM, CnP/BN);
    cls_kernel<<<g2, 512, SMEM_CLS>>>(bbias, lab);
    fin1<<<Bn/256, 256>>>();
    fin2<<<1,1>>>(out);
}

// round 6
// speedup vs baseline: 2.2758x; 2.2758x over previous
#include <cuda_runtime.h>
#include <cuda_bf16.h>
#include <cstdint>
#include <cmath>

#define Bn 8192
#define Dn 2048
#define Cn 751
#define CnP 768
#define NCAMS 16
#define MARGINF 0.3f
#define IT (1.0f/0.07f)
#define L2E 1.44269504f
#define LN2f 0.69314718f
#define CEXP (IT*L2E)
#define BIGF 1.0e9f
#define L_TRI 0.5f
#define L_ST 0.3f

#define BM 128
#define BK 32                 // bf16 elements per k-step (64 bytes/row)
#define KT 64                 // k-steps (Dn/BK)
#define NBLK (Bn/BM)          // 64 row/col blocks
#define NTILE (NBLK*(NBLK+1)/2)   // 2080 upper-tri tiles
#define STG 16384             // stage: A 8KB + B 8KB
#define SM_REACH (4*STG)      // 65536
#define SM_SQ  (SM_REACH+1024)
#define SM_INV (SM_SQ+512)
#define SM_TS  (SM_INV+512)
#define SM_LAB (SM_TS+512)
#define SM_CAM (SM_LAB+512)
#define SMEM_PAIR (SM_CAM+512)   // 69120
#define SMEM_CLS (4*STG+1024)

// swizzled smem offset: 64B rows, 16B chunks, perm = c ^ ((row>>1)&3)
#define SW(row, ch) ((row)*64 + ((((ch) ^ (((row)>>1)&3)))<<4))

// ---------------- device scratch ----------------
__device__ __nv_bfloat16 g_Fb[(size_t)Bn*Dn];   // 32 MB
__device__ __nv_bfloat16 g_Wb[(size_t)CnP*Dn];  // 3 MB
__device__ float    g_sq[Bn], g_invn[Bn];
__device__ float    g_sume[Bn], g_spos[Bn], g_cpos[Bn];
__device__ unsigned g_hp[Bn], g_hn[Bn];
__device__ float    g_sume_cls[Bn], g_lab_logit[Bn];
__device__ float    g_acc[8];

__device__ __forceinline__ unsigned f2o(float f){
    unsigned u = __float_as_uint(f);
    return (u & 0x80000000u) ? ~u : (u | 0x80000000u);
}
__device__ __forceinline__ float o2f(unsigned u){
    return __uint_as_float((u & 0x80000000u) ? (u & 0x7fffffffu) : ~u);
}
__device__ __forceinline__ uint32_t pack_bf(float a, float b){
    __nv_bfloat162 t = __floats2bfloat162_rn(a, b);
    return *reinterpret_cast<uint32_t*>(&t);
}
__device__ __forceinline__ float sq2(uint32_t u){
    __nv_bfloat162 h = *reinterpret_cast<__nv_bfloat162*>(&u);
    float2 f = __bfloat1622float2(h);
    return f.x*f.x + f.y*f.y;
}

#define CP16(dst, src) asm volatile("cp.async.cg.shared.global [%0], [%1], 16;" :: "r"(dst), "l"(src) : "memory")
#define CP_COMMIT()    asm volatile("cp.async.commit_group;" ::: "memory")
#define CP_WAIT(n)     asm volatile("cp.async.wait_group %0;" :: "n"(n) : "memory")

__device__ __forceinline__ void ldm4(uint32_t &r0, uint32_t &r1, uint32_t &r2, uint32_t &r3, uint32_t addr){
    asm volatile("ldmatrix.sync.aligned.m8n8.x4.shared.b16 {%0,%1,%2,%3}, [%4];"
        : "=r"(r0), "=r"(r1), "=r"(r2), "=r"(r3) : "r"(addr));
}
__device__ __forceinline__ void mma16816(float* d, const uint32_t* a, const uint32_t* b){
    asm volatile("mma.sync.aligned.m16n8k16.row.col.f32.bf16.bf16.f32 "
        "{%0,%1,%2,%3}, {%4,%5,%6,%7}, {%8,%9}, {%0,%1,%2,%3};"
        : "+f"(d[0]), "+f"(d[1]), "+f"(d[2]), "+f"(d[3])
        : "r"(a[0]), "r"(a[1]), "r"(a[2]), "r"(a[3]), "r"(b[0]), "r"(b[1]));
}

// ---------------- conversion / init / norms ----------------
__global__ void convert_F_kernel(const float* __restrict__ F){
    size_t i = ((size_t)blockIdx.x*blockDim.x + threadIdx.x)*8;
    float4 v0 = *(const float4*)(F+i);
    float4 v1 = *(const float4*)(F+i+4);
    uint4 o;
    o.x = pack_bf(v0.x, v0.y); o.y = pack_bf(v0.z, v0.w);
    o.z = pack_bf(v1.x, v1.y); o.w = pack_bf(v1.z, v1.w);
    *(uint4*)(g_Fb + i) = o;
}
__global__ void convert_W_kernel(const float* __restrict__ W){
    size_t i = ((size_t)blockIdx.x*blockDim.x + threadIdx.x)*8;
    size_t row = i / Dn;
    uint4 o;
    if (row < Cn){
        float4 v0 = *(const float4*)(W+i);
        float4 v1 = *(const float4*)(W+i+4);
        o.x = pack_bf(v0.x, v0.y); o.y = pack_bf(v0.z, v0.w);
        o.z = pack_bf(v1.x, v1.y); o.w = pack_bf(v1.z, v1.w);
    } else { o.x=o.y=o.z=o.w=0u; }
    *(uint4*)(g_Wb + i) = o;
}
__global__ void init_kernel(){
    int i = blockIdx.x*blockDim.x + threadIdx.x;
    if (i < Bn){
        g_sume[i]=0.f; g_spos[i]=0.f; g_cpos[i]=0.f;
        g_hp[i]=f2o(-BIGF); g_hn[i]=f2o(BIGF);
        g_sume_cls[i]=0.f; g_lab_logit[i]=0.f;
    }
    if (i < 8) g_acc[i]=0.f;
}
__global__ void norm_kernel(){
    int row  = blockIdx.x*(blockDim.x>>5) + (threadIdx.x>>5);
    int lane = threadIdx.x & 31;
    const uint4* p = (const uint4*)(g_Fb + (size_t)row*Dn);
    float s = 0.f;
    #pragma unroll
    for (int i = lane; i < Dn/8; i += 32){
        uint4 v = p[i];
        s += sq2(v.x) + sq2(v.y) + sq2(v.z) + sq2(v.w);
    }
    #pragma unroll
    for (int o=16;o;o>>=1) s += __shfl_xor_sync(0xffffffffu, s, o);
    if (lane==0){ g_sq[row]=s; g_invn[row]=rsqrtf(s); }
}

// ---------------- fused Gram kernel: upper-triangle tiles, dual-side epilogue ----------------
__global__ __launch_bounds__(256) void pair_kernel(
    const int* __restrict__ lab, const int* __restrict__ cam,
    const float* __restrict__ ts, const float* __restrict__ reach)
{
    extern __shared__ char smem[];
    uint32_t sb = (uint32_t)__cvta_generic_to_shared(smem);
    int tid = threadIdx.x, lane = tid&31, wid = tid>>5;
    int wm = wid&3, wn = wid>>2;        // 4 row-slots x 2 col-slots

    // decode upper-triangle tile (I <= J)
    int t = blockIdx.x;
    int I = (int)((129.0 - sqrt(16641.0 - 8.0*(double)t))*0.5);
    if (I < 0) I = 0; if (I > 63) I = 63;
    while (I < 63 && ((I+1)*(129-(I+1)))/2 <= t) I++;
    while (((I)*(129-I))/2 > t) I--;
    int J = I + (t - (I*(129-I))/2);
    bool diag = (I == J);
    int row0 = I*BM, col0 = J*BM;

    float* s_reach=(float*)(smem+SM_REACH);
    float* s_sq  =(float*)(smem+SM_SQ);
    float* s_invn=(float*)(smem+SM_INV);
    float* s_ts  =(float*)(smem+SM_TS);
    int*   s_lab =(int*)  (smem+SM_LAB);
    int*   s_cam =(int*)  (smem+SM_CAM);
    if (tid < 256) s_reach[tid] = reach[tid];
    if (tid < 128){
        int cj = col0 + tid;
        s_sq[tid]=g_sq[cj]; s_invn[tid]=g_invn[cj]; s_ts[tid]=ts[cj];
        s_lab[tid]=lab[cj]; s_cam[tid]=cam[cj];
    }

    // loaders: 2 chunks of A + 2 of B per thread per stage
    int rA = tid>>1, cA = (tid&1)*2;
    uint32_t dA0 = SW(rA, cA), dA1 = SW(rA, cA+1);
    uint32_t dB0 = 8192 + dA0, dB1 = 8192 + dA1;
    const __nv_bfloat16* gA = g_Fb + (size_t)(row0+rA)*Dn + cA*8;
    const __nv_bfloat16* gB = g_Fb + (size_t)(col0+rA)*Dn + cA*8;

    // ldmatrix per-lane offsets
    int q = lane>>3, rr = lane&7;
    int offA_ld[2][2], offB_ld[4][2];
    #pragma unroll
    for (int mt=0; mt<2; mt++)
        #pragma unroll
        for (int ks=0; ks<2; ks++){
            int row = wm*32 + mt*16 + rr + (q&1)*8;
            offA_ld[mt][ks] = SW(row, ks*2 + (q>>1));
        }
    #pragma unroll
    for (int nt4=0; nt4<4; nt4++)
        #pragma unroll
        for (int ks=0; ks<2; ks++){
            int row = wn*64 + nt4*16 + rr + (q>>1)*8;
            offB_ld[nt4][ks] = 8192 + SW(row, ks*2 + (q&1));
        }

    float acc[2][8][4];
    #pragma unroll
    for (int i=0;i<2;i++)
        #pragma unroll
        for (int j=0;j<8;j++)
            #pragma unroll
            for (int e=0;e<4;e++) acc[i][j][e]=0.f;

    #define PLOAD(j) do { \
        uint32_t _st = sb + ((j)&3)*STG; \
        size_t _ko = (size_t)(j)*BK; \
        CP16(_st+dA0, gA+_ko); CP16(_st+dA1, gA+_ko+8); \
        CP16(_st+dB0, gB+_ko); CP16(_st+dB1, gB+_ko+8); \
    } while(0)

    PLOAD(0); CP_COMMIT();
    PLOAD(1); CP_COMMIT();
    PLOAD(2); CP_COMMIT();

    for (int j=0; j<KT; j++){
        CP_WAIT(2);
        __syncthreads();
        if (j+3 < KT) PLOAD(j+3);
        CP_COMMIT();
        uint32_t st = sb + (j&3)*STG;
        #pragma unroll
        for (int ks=0; ks<2; ks++){
            uint32_t a[2][4], b[8][2];
            ldm4(a[0][0],a[0][1],a[0][2],a[0][3], st + offA_ld[0][ks]);
            ldm4(a[1][0],a[1][1],a[1][2],a[1][3], st + offA_ld[1][ks]);
            #pragma unroll
            for (int nt4=0; nt4<4; nt4++)
                ldm4(b[nt4*2][0],b[nt4*2][1],b[nt4*2+1][0],b[nt4*2+1][1], st + offB_ld[nt4][ks]);
            #pragma unroll
            for (int mt=0; mt<2; mt++)
                #pragma unroll
                for (int nt=0; nt<8; nt++)
                    mma16816(acc[mt][nt], a[mt], b[nt]);
        }
    }
    #undef PLOAD

    // ---- dual-side fused epilogue ----
    int   r4[4], labi[4], cami[4];
    float sqi[4], ari[4], tsi[4];
    #pragma unroll
    for (int x=0;x<4;x++){
        int ri = row0 + wm*32 + (x>>1)*16 + (x&1)*8 + (lane>>2);
        r4[x]=ri; sqi[x]=g_sq[ri]; ari[x]=g_invn[ri]*CEXP;
        tsi[x]=ts[ri]; labi[x]=lab[ri]; cami[x]=cam[ri];
    }
    float sume4[4], spos4[4], cpos4[4], hp4[4], hn4[4];
    #pragma unroll
    for (int x=0;x<4;x++){ sume4[x]=0.f; spos4[x]=0.f; cpos4[x]=0.f; hp4[x]=-BIGF; hn4[x]=BIGF; }

    #pragma unroll
    for (int nt=0; nt<8; nt++){
        #pragma unroll
        for (int u=0; u<2; u++){
            int cl = wn*64 + nt*8 + (lane&3)*2 + u;
            int cj = col0 + cl;
            float sqj=s_sq[cl], invj=s_invn[cl], tsj=s_ts[cl];
            int labj=s_lab[cl], camj=s_cam[cl];
            float hpC=-BIGF, hnC=BIGF, sumeC=0.f, sposC=0.f, cposC=0.f;
            #pragma unroll
            for (int mt=0; mt<2; mt++){
                #pragma unroll
                for (int h=0; h<2; h++){
                    int x = mt*2 + h;
                    float g  = acc[mt][nt][h*2+u];
                    float d2 = fmaxf(fmaf(-2.f, g, sqi[x] + sqj), 0.f);
                    bool eye  = (r4[x] == cj);
                    bool same = (labi[x] == labj);
                    bool sne  = same && !eye;
                    float tt = fmaf(g*ari[x], invj, -CEXP);
                    float ev; asm("ex2.approx.ftz.f32 %0, %1;" : "=f"(ev) : "f"(tt));
                    float dt = fabsf(tsi[x] - tsj);
                    // row side (anchor = r4[x])
                    if (sne) hp4[x] = fmaxf(hp4[x], d2);
                    else     hn4[x] = fminf(hn4[x], d2);
                    sume4[x] += ev;
                    if (sne && dt <= s_reach[cami[x]*NCAMS + camj]){
                        spos4[x] += fmaf(tt, LN2f, IT); cpos4[x] += 1.f;
                    }
                    // column side (anchor = cj), skip on diagonal tiles
                    if (!diag){
                        if (sne) hpC = fmaxf(hpC, d2);
                        else     hnC = fminf(hnC, d2);
                        sumeC += ev;
                        if (sne && dt <= s_reach[camj*NCAMS + cami[x]]){
                            sposC += fmaf(tt, LN2f, IT); cposC += 1.f;
                        }
                    }
                }
            }
            if (!diag){
                #pragma unroll
                for (int o=4; o<=16; o<<=1){
                    sumeC += __shfl_xor_sync(0xffffffffu, sumeC, o);
                    sposC += __shfl_xor_sync(0xffffffffu, sposC, o);
                    cposC += __shfl_xor_sync(0xffffffffu, cposC, o);
                    hpC = fmaxf(hpC, __shfl_xor_sync(0xffffffffu, hpC, o));
                    hnC = fminf(hnC, __shfl_xor_sync(0xffffffffu, hnC, o));
                }
                if ((lane>>2) == 0){
                    atomicAdd(&g_sume[cj], sumeC);
                    if (cposC > 0.f){ atomicAdd(&g_spos[cj], sposC); atomicAdd(&g_cpos[cj], cposC); }
                    if (hpC > -BIGF) atomicMax(&g_hp[cj], f2o(hpC));
                    atomicMin(&g_hn[cj], f2o(hnC));
                }
            }
        }
    }

    // row-side merge: reduce over (lane&3) groups
    #pragma unroll
    for (int o=1; o<=2; o<<=1){
        #pragma unroll
        for (int x=0;x<4;x++){
            sume4[x] += __shfl_xor_sync(0xffffffffu, sume4[x], o);
            spos4[x] += __shfl_xor_sync(0xffffffffu, spos4[x], o);
            cpos4[x] += __shfl_xor_sync(0xffffffffu, cpos4[x], o);
            hp4[x] = fmaxf(hp4[x], __shfl_xor_sync(0xffffffffu, hp4[x], o));
            hn4[x] = fminf(hn4[x], __shfl_xor_sync(0xffffffffu, hn4[x], o));
        }
    }
    if ((lane&3)==0){
        #pragma unroll
        for (int x=0;x<4;x++){
            int ri = r4[x];
            atomicAdd(&g_sume[ri], sume4[x]);
            if (cpos4[x] > 0.f){ atomicAdd(&g_spos[ri], spos4[x]); atomicAdd(&g_cpos[ri], cpos4[x]); }
            if (hp4[x] > -BIGF) atomicMax(&g_hp[ri], f2o(hp4[x]));
            atomicMin(&g_hn[ri], f2o(hn4[x]));
        }
    }
}

// ---------------- classifier (bf16 mma.sync, 128x128 tiles) ----------------
__global__ __launch_bounds__(256) void cls_kernel(
    const float* __restrict__ bbias, const int* __restrict__ lab)
{
    extern __shared__ char smem[];
    uint32_t sb = (uint32_t)__cvta_generic_to_shared(smem);
    int tid = threadIdx.x, lane = tid&31, wid = tid>>5;
    int wm = wid&3, wn = wid>>2;
    int row0 = blockIdx.x*BM;
    int col0 = blockIdx.y*BM;
    float* s_b = (float*)(smem + 4*STG);
    if (tid < 128){
        int cj = col0 + tid;
        s_b[tid] = (cj < Cn) ? bbias[cj] : 0.f;
    }

    int rA = tid>>1, cA = (tid&1)*2;
    uint32_t dA0 = SW(rA, cA), dA1 = SW(rA, cA+1);
    uint32_t dB0 = 8192 + dA0, dB1 = 8192 + dA1;
    const __nv_bfloat16* gA = g_Fb + (size_t)(row0+rA)*Dn + cA*8;
    const __nv_bfloat16* gB = g_Wb + (size_t)(col0+rA)*Dn + cA*8;

    int q = lane>>3, rr = lane&7;
    int offA_ld[2][2], offB_ld[4][2];
    #pragma unroll
    for (int mt=0; mt<2; mt++)
        #pragma unroll
        for (int ks=0; ks<2; ks++){
            int row = wm*32 + mt*16 + rr + (q&1)*8;
            offA_ld[mt][ks] = SW(row, ks*2 + (q>>1));
        }
    #pragma unroll
    for (int nt4=0; nt4<4; nt4++)
        #pragma unroll
        for (int ks=0; ks<2; ks++){
            int row = wn*64 + nt4*16 + rr + (q>>1)*8;
            offB_ld[nt4][ks] = 8192 + SW(row, ks*2 + (q&1));
        }

    float acc[2][8][4];
    #pragma unroll
    for (int i=0;i<2;i++)
        #pragma unroll
        for (int j=0;j<8;j++)
            #pragma unroll
            for (int e=0;e<4;e++) acc[i][j][e]=0.f;

    #define CLOAD(j) do { \
        uint32_t _st = sb + ((j)&3)*STG; \
        size_t _ko = (size_t)(j)*BK; \
        CP16(_st+dA0, gA+_ko); CP16(_st+dA1, gA+_ko+8); \
        CP16(_st+dB0, gB+_ko); CP16(_st+dB1, gB+_ko+8); \
    } while(0)

    CLOAD(0); CP_COMMIT();
    CLOAD(1); CP_COMMIT();
    CLOAD(2); CP_COMMIT();

    for (int j=0; j<KT; j++){
        CP_WAIT(2);
        __syncthreads();
        if (j+3 < KT) CLOAD(j+3);
        CP_COMMIT();
        uint32_t st = sb + (j&3)*STG;
        #pragma unroll
        for (int ks=0; ks<2; ks++){
            uint32_t a[2][4], b[8][2];
            ldm4(a[0][0],a[0][1],a[0][2],a[0][3], st + offA_ld[0][ks]);
            ldm4(a[1][0],a[1][1],a[1][2],a[1][3], st + offA_ld[1][ks]);
            #pragma unroll
            for (int nt4=0; nt4<4; nt4++)
                ldm4(b[nt4*2][0],b[nt4*2][1],b[nt4*2+1][0],b[nt4*2+1][1], st + offB_ld[nt4][ks]);
            #pragma unroll
            for (int mt=0; mt<2; mt++)
                #pragma unroll
                for (int nt=0; nt<8; nt++)
                    mma16816(acc[mt][nt], a[mt], b[nt]);
        }
    }
    #undef CLOAD

    float se4[4];
    #pragma unroll
    for (int x=0;x<4;x++) se4[x]=0.f;
    #pragma unroll
    for (int mt=0; mt<2; mt++)
        #pragma unroll
        for (int h=0; h<2; h++){
            int x = mt*2 + h;
            int ri = row0 + wm*32 + mt*16 + h*8 + (lane>>2);
            int labi = lab[ri];
            #pragma unroll
            for (int nt=0; nt<8; nt++){
                int cl = wn*64 + nt*8 + (lane&3)*2;
                #pragma unroll
                for (int u=0; u<2; u++){
                    int clu = cl+u, cj = col0+clu;
                    float logit = acc[mt][nt][h*2+u] + s_b[clu];
                    if (cj < Cn){
                        se4[x] += __expf(logit);
                        if (cj == labi) g_lab_logit[ri] = logit;
                    }
                }
            }
        }
    #pragma unroll
    for (int o=1;o<=2;o<<=1)
        #pragma unroll
        for (int x=0;x<4;x++)
            se4[x] += __shfl_xor_sync(0xffffffffu, se4[x], o);
    if ((lane&3)==0){
        #pragma unroll
        for (int x=0;x<4;x++){
            int ri = row0 + wm*32 + (x>>1)*16 + (x&1)*8 + (lane>>2);
            atomicAdd(&g_sume_cls[ri], se4[x]);
        }
    }
}

// ---------------- final reductions ----------------
__global__ void fin1(){
    int i = blockIdx.x*blockDim.x + threadIdx.x;
    float tri=0.f, nv=0.f, stn=0.f, stc=0.f, cls=0.f;
    if (i < Bn){
        float lse = IT + logf(g_sume[i]);
        stn = g_spos[i] - g_cpos[i]*lse;
        stc = g_cpos[i];
        float hp = o2f(g_hp[i]), hn = o2f(g_hn[i]);
        bool valid = hp > -1.0e8f;
        tri = valid ? fmaxf(hp - hn + MARGINF, 0.f) : 0.f;
        nv  = valid ? 1.f : 0.f;
        cls = logf(g_sume_cls[i]) - g_lab_logit[i];
    }
    #pragma unroll
    for (int o=16;o;o>>=1){
        tri += __shfl_down_sync(0xffffffffu, tri, o);
        nv  += __shfl_down_sync(0xffffffffu, nv , o);
        stn += __shfl_down_sync(0xffffffffu, stn, o);
        stc += __shfl_down_sync(0xffffffffu, stc, o);
        cls += __shfl_down_sync(0xffffffffu, cls, o);
    }
    if ((threadIdx.x & 31) == 0){
        atomicAdd(&g_acc[0], tri);
        atomicAdd(&g_acc[1], nv);
        atomicAdd(&g_acc[2], stn);
        atomicAdd(&g_acc[3], stc);
        atomicAdd(&g_acc[4], cls);
    }
}
__global__ void fin2(float* out){
    float nv = g_acc[1], npos = g_acc[3];
    float loss_id  = g_acc[4] / (float)Bn;
    float loss_tri = (nv   > 0.f) ? g_acc[0] / fmaxf(nv,   1.f) : 0.f;
    float loss_st  = (npos > 0.f) ? (-g_acc[2]) / fmaxf(npos, 1.f) : 0.f;
    out[0] = loss_id + L_TRI*loss_tri + L_ST*loss_st;
}

// ---------------- launch ----------------
extern "C" void kernel_launch(void* const* d_in, const int* in_sizes, int n_in,
                              void* d_out, int out_size){
    const float* F     = (const float*)d_in[0];
    const int*   lab   = (const int*)  d_in[1];
    const int*   cam   = (const int*)  d_in[2];
    const float* ts    = (const float*)d_in[3];
    const float* reach = (const float*)d_in[4];
    const float* W     = (const float*)d_in[5];
    const float* bbias = (const float*)d_in[6];
    float* out = (float*)d_out;

    cudaFuncSetAttribute(pair_kernel, cudaFuncAttributeMaxDynamicSharedMemorySize, SMEM_PAIR);
    cudaFuncSetAttribute(cls_kernel,  cudaFuncAttributeMaxDynamicSharedMemorySize, SMEM_CLS);

    convert_F_kernel<<<(Bn*(size_t)Dn/8)/256, 256>>>(F);
    convert_W_kernel<<<((size_t)CnP*Dn/8)/256, 256>>>(W);
    init_kernel<<<(Bn+255)/256, 256>>>();
    norm_kernel<<<Bn/8, 256>>>();
    pair_kernel<<<NTILE, 256, SMEM_PAIR>>>(lab, cam, ts, reach);
    dim3 g2(Bn/BM, CnP/BM);
    cls_kernel<<<g2, 256, SMEM_CLS>>>(bbias, lab);
    fin1<<<Bn/256, 256>>>();
    fin2<<<1,1>>>(out);
}

// round 7
// speedup vs baseline: 3.0963x; 1.3606x over previous
#include <cuda_runtime.h>
#include <cuda_bf16.h>
#include <cstdint>
#include <cmath>

#define Bn 8192
#define Dn 2048
#define Cn 751
#define CnP 768
#define NCAMS 16
#define MARGINF 0.3f
#define IT (1.0f/0.07f)
#define L2E 1.44269504f
#define LN2f 0.69314718f
#define CEXP (IT*L2E)
#define BIGF 1.0e9f
#define L_TRI 0.5f
#define L_ST 0.3f

#define BM 128
#define BK 64                 // bf16 elements per k-slab (128 bytes/row)
#define KT 32                 // k-slabs (Dn/BK)
#define NBLK (Bn/BM)          // 64
#define NTILE (NBLK*(NBLK+1)/2)   // 2080 upper-tri tiles
#define STG 32768             // stage: A 16KB + B 16KB
#define NST 3
#define SM_REACH (NST*STG)    // 98304
#define SM_SQ  (SM_REACH+1024)
#define SM_INV (SM_SQ+512)
#define SM_TS  (SM_INV+512)
#define SM_LAB (SM_TS+512)
#define SM_CAM (SM_LAB+512)
#define SMEM_PAIR (SM_CAM+512)    // 101888
#define SMEM_CLS (NST*STG+1024)   // 99328

// swizzle for 128B rows: 16B chunks, perm = c ^ (row&7)
#define SW2(row, ch) ((row)*128 + ((((ch) ^ ((row)&7)))<<4))

// ---------------- device scratch ----------------
__device__ __nv_bfloat16 g_Fb[(size_t)Bn*Dn];   // 32 MB
__device__ __nv_bfloat16 g_Wb[(size_t)CnP*Dn];  // 3 MB
__device__ float    g_sq[Bn], g_invn[Bn];
__device__ float    g_sume[Bn], g_spos[Bn], g_cpos[Bn];
__device__ unsigned g_hp[Bn], g_hn[Bn];
__device__ float    g_sume_cls[Bn], g_lab_logit[Bn];
__device__ float    g_acc[8];

__device__ __forceinline__ unsigned f2o(float f){
    unsigned u = __float_as_uint(f);
    return (u & 0x80000000u) ? ~u : (u | 0x80000000u);
}
__device__ __forceinline__ float o2f(unsigned u){
    return __uint_as_float((u & 0x80000000u) ? (u & 0x7fffffffu) : ~u);
}
__device__ __forceinline__ uint32_t pack_bf(float a, float b){
    __nv_bfloat162 t = __floats2bfloat162_rn(a, b);
    return *reinterpret_cast<uint32_t*>(&t);
}
__device__ __forceinline__ float sq2(uint32_t u){
    __nv_bfloat162 h = *reinterpret_cast<__nv_bfloat162*>(&u);
    float2 f = __bfloat1622float2(h);
    return f.x*f.x + f.y*f.y;
}

#define CP16(dst, src) asm volatile("cp.async.cg.shared.global [%0], [%1], 16;" :: "r"(dst), "l"(src) : "memory")
#define CP_COMMIT()    asm volatile("cp.async.commit_group;" ::: "memory")
#define CP_WAIT(n)     asm volatile("cp.async.wait_group %0;" :: "n"(n) : "memory")

__device__ __forceinline__ void ldm4(uint32_t &r0, uint32_t &r1, uint32_t &r2, uint32_t &r3, uint32_t addr){
    asm volatile("ldmatrix.sync.aligned.m8n8.x4.shared.b16 {%0,%1,%2,%3}, [%4];"
        : "=r"(r0), "=r"(r1), "=r"(r2), "=r"(r3) : "r"(addr));
}
__device__ __forceinline__ void mma16816(float* d, const uint32_t* a, const uint32_t* b){
    asm volatile("mma.sync.aligned.m16n8k16.row.col.f32.bf16.bf16.f32 "
        "{%0,%1,%2,%3}, {%4,%5,%6,%7}, {%8,%9}, {%0,%1,%2,%3};"
        : "+f"(d[0]), "+f"(d[1]), "+f"(d[2]), "+f"(d[3])
        : "r"(a[0]), "r"(a[1]), "r"(a[2]), "r"(a[3]), "r"(b[0]), "r"(b[1]));
}

// ---------------- conversion / norms(+init) ----------------
__global__ void convert_F_kernel(const float* __restrict__ F){
    size_t i = ((size_t)blockIdx.x*blockDim.x + threadIdx.x)*8;
    float4 v0 = *(const float4*)(F+i);
    float4 v1 = *(const float4*)(F+i+4);
    uint4 o;
    o.x = pack_bf(v0.x, v0.y); o.y = pack_bf(v0.z, v0.w);
    o.z = pack_bf(v1.x, v1.y); o.w = pack_bf(v1.z, v1.w);
    *(uint4*)(g_Fb + i) = o;
}
__global__ void convert_W_kernel(const float* __restrict__ W){
    size_t i = ((size_t)blockIdx.x*blockDim.x + threadIdx.x)*8;
    size_t row = i / Dn;
    uint4 o;
    if (row < Cn){
        float4 v0 = *(const float4*)(W+i);
        float4 v1 = *(const float4*)(W+i+4);
        o.x = pack_bf(v0.x, v0.y); o.y = pack_bf(v0.z, v0.w);
        o.z = pack_bf(v1.x, v1.y); o.w = pack_bf(v1.z, v1.w);
    } else { o.x=o.y=o.z=o.w=0u; }
    *(uint4*)(g_Wb + i) = o;
}
__global__ void norm_kernel(){
    int row  = blockIdx.x*(blockDim.x>>5) + (threadIdx.x>>5);
    int lane = threadIdx.x & 31;
    const uint4* p = (const uint4*)(g_Fb + (size_t)row*Dn);
    float s = 0.f;
    #pragma unroll
    for (int i = lane; i < Dn/8; i += 32){
        uint4 v = p[i];
        s += sq2(v.x) + sq2(v.y) + sq2(v.z) + sq2(v.w);
    }
    #pragma unroll
    for (int o=16;o;o>>=1) s += __shfl_xor_sync(0xffffffffu, s, o);
    if (lane==0){
        g_sq[row]=s; g_invn[row]=rsqrtf(s);
        g_sume[row]=0.f; g_spos[row]=0.f; g_cpos[row]=0.f;
        g_hp[row]=f2o(-BIGF); g_hn[row]=f2o(BIGF);
        g_sume_cls[row]=0.f; g_lab_logit[row]=0.f;
    }
    if (blockIdx.x==0 && threadIdx.x<8) g_acc[threadIdx.x]=0.f;
}

// ---------------- fused Gram kernel: upper-tri tiles, BK=64, dual-side epilogue ----------------
__global__ __launch_bounds__(256,2) void pair_kernel(
    const int* __restrict__ lab, const int* __restrict__ cam,
    const float* __restrict__ ts, const float* __restrict__ reach)
{
    extern __shared__ char smem[];
    uint32_t sb = (uint32_t)__cvta_generic_to_shared(smem);
    int tid = threadIdx.x, lane = tid&31, wid = tid>>5;
    int wm = wid&3, wn = wid>>2;

    // decode upper-triangle tile (I <= J)
    int t = blockIdx.x;
    int I = (int)((129.0 - sqrt(16641.0 - 8.0*(double)t))*0.5);
    if (I < 0) I = 0; if (I > 63) I = 63;
    while (I < 63 && ((I+1)*(129-(I+1)))/2 <= t) I++;
    while (((I)*(129-I))/2 > t) I--;
    int J = I + (t - (I*(129-I))/2);
    bool diag = (I == J);
    int row0 = I*BM, col0 = J*BM;

    float* s_reach=(float*)(smem+SM_REACH);
    float* s_sq  =(float*)(smem+SM_SQ);
    float* s_invn=(float*)(smem+SM_INV);
    float* s_ts  =(float*)(smem+SM_TS);
    int*   s_lab =(int*)  (smem+SM_LAB);
    int*   s_cam =(int*)  (smem+SM_CAM);
    if (tid < 256) s_reach[tid] = reach[tid];
    if (tid < 128){
        int cj = col0 + tid;
        s_sq[tid]=g_sq[cj]; s_invn[tid]=g_invn[cj]; s_ts[tid]=ts[cj];
        s_lab[tid]=lab[cj]; s_cam[tid]=cam[cj];
    }

    // loaders: 4 chunks of A + 4 of B per thread per stage (8 chunks/row of 128B)
    int rL = tid>>3, cL = tid&7;
    uint32_t dA = SW2(rL, cL);
    const __nv_bfloat16* gA = g_Fb + (size_t)(row0+rL)*Dn + cL*8;
    const __nv_bfloat16* gB = g_Fb + (size_t)(col0+rL)*Dn + cL*8;

    // per-lane fragment row bases (swizzle XOR shared: row&7 == rr for all)
    int q = lane>>3, rr = lane&7;
    int rowA[2], rowB[4];
    #pragma unroll
    for (int mt=0; mt<2; mt++) rowA[mt] = (wm*32 + mt*16 + rr + (q&1)*8)*128;
    #pragma unroll
    for (int nt4=0; nt4<4; nt4++) rowB[nt4] = 16384 + (wn*64 + nt4*16 + rr + (q>>1)*8)*128;
    int qhi = q>>1, qlo = q&1;

    float acc[2][8][4];
    #pragma unroll
    for (int i=0;i<2;i++)
        #pragma unroll
        for (int j=0;j<8;j++)
            #pragma unroll
            for (int e=0;e<4;e++) acc[i][j][e]=0.f;

    #define PLOAD(j, stq) do { \
        uint32_t _st = sb + (stq)*STG; \
        size_t _ko = (size_t)(j)*BK; \
        _Pragma("unroll") \
        for (int _i=0;_i<4;_i++){ \
            CP16(_st+dA+4096*_i,       gA + (size_t)(32*_i)*Dn + _ko); \
            CP16(_st+16384+dA+4096*_i, gB + (size_t)(32*_i)*Dn + _ko); \
        } \
    } while(0)

    PLOAD(0,0); CP_COMMIT();
    PLOAD(1,1); CP_COMMIT();

    int cs = 0, ls = 2;
    for (int j=0; j<KT; j++){
        CP_WAIT(1);
        __syncthreads();
        if (j+2 < KT){
            PLOAD(j+2, ls);
            ls++; if (ls==NST) ls=0;
        }
        CP_COMMIT();
        uint32_t st = sb + cs*STG;
        cs++; if (cs==NST) cs=0;
        #pragma unroll
        for (int ks=0; ks<4; ks++){
            uint32_t chA = st + ((((ks*2+qhi) ^ rr))<<4);
            uint32_t chB = st + ((((ks*2+qlo) ^ rr))<<4);
            uint32_t a[2][4], b[8][2];
            ldm4(a[0][0],a[0][1],a[0][2],a[0][3], chA + rowA[0]);
            ldm4(a[1][0],a[1][1],a[1][2],a[1][3], chA + rowA[1]);
            #pragma unroll
            for (int nt4=0; nt4<4; nt4++)
                ldm4(b[nt4*2][0],b[nt4*2][1],b[nt4*2+1][0],b[nt4*2+1][1], chB + rowB[nt4]);
            #pragma unroll
            for (int mt=0; mt<2; mt++)
                #pragma unroll
                for (int nt=0; nt<8; nt++)
                    mma16816(acc[mt][nt], a[mt], b[nt]);
        }
    }
    #undef PLOAD

    // ---- dual-side fused epilogue ----
    int   r4[4], labi[4], cami[4];
    float sqi[4], ari[4], tsi[4];
    #pragma unroll
    for (int x=0;x<4;x++){
        int ri = row0 + wm*32 + (x>>1)*16 + (x&1)*8 + (lane>>2);
        r4[x]=ri; sqi[x]=g_sq[ri]; ari[x]=g_invn[ri]*CEXP;
        tsi[x]=ts[ri]; labi[x]=lab[ri]; cami[x]=cam[ri];
    }
    float sume4[4], spos4[4], cpos4[4], hp4[4], hn4[4];
    #pragma unroll
    for (int x=0;x<4;x++){ sume4[x]=0.f; spos4[x]=0.f; cpos4[x]=0.f; hp4[x]=-BIGF; hn4[x]=BIGF; }

    #pragma unroll
    for (int nt=0; nt<8; nt++){
        #pragma unroll
        for (int u=0; u<2; u++){
            int cl = wn*64 + nt*8 + (lane&3)*2 + u;
            int cj = col0 + cl;
            float sqj=s_sq[cl], invj=s_invn[cl], tsj=s_ts[cl];
            int labj=s_lab[cl], camj=s_cam[cl];
            float hpC=-BIGF, hnC=BIGF, sumeC=0.f, sposC=0.f, cposC=0.f;
            #pragma unroll
            for (int mt=0; mt<2; mt++){
                #pragma unroll
                for (int h=0; h<2; h++){
                    int x = mt*2 + h;
                    float g  = acc[mt][nt][h*2+u];
                    float d2 = fmaxf(fmaf(-2.f, g, sqi[x] + sqj), 0.f);
                    bool eye  = (r4[x] == cj);
                    bool same = (labi[x] == labj);
                    bool sne  = same && !eye;
                    float tt = fmaf(g*ari[x], invj, -CEXP);
                    float ev; asm("ex2.approx.ftz.f32 %0, %1;" : "=f"(ev) : "f"(tt));
                    float dt = fabsf(tsi[x] - tsj);
                    // row side
                    if (sne) hp4[x] = fmaxf(hp4[x], d2);
                    else     hn4[x] = fminf(hn4[x], d2);
                    sume4[x] += ev;
                    if (sne && dt <= s_reach[cami[x]*NCAMS + camj]){
                        spos4[x] += fmaf(tt, LN2f, IT); cpos4[x] += 1.f;
                    }
                    // column side (skip on diagonal tiles)
                    if (!diag){
                        if (sne) hpC = fmaxf(hpC, d2);
                        else     hnC = fminf(hnC, d2);
                        sumeC += ev;
                        if (sne && dt <= s_reach[camj*NCAMS + cami[x]]){
                            sposC += fmaf(tt, LN2f, IT); cposC += 1.f;
                        }
                    }
                }
            }
            if (!diag){
                #pragma unroll
                for (int o=4; o<=16; o<<=1){
                    sumeC += __shfl_xor_sync(0xffffffffu, sumeC, o);
                    sposC += __shfl_xor_sync(0xffffffffu, sposC, o);
                    cposC += __shfl_xor_sync(0xffffffffu, cposC, o);
                    hpC = fmaxf(hpC, __shfl_xor_sync(0xffffffffu, hpC, o));
                    hnC = fminf(hnC, __shfl_xor_sync(0xffffffffu, hnC, o));
                }
                if ((lane>>2) == 0){
                    atomicAdd(&g_sume[cj], sumeC);
                    if (cposC > 0.f){ atomicAdd(&g_spos[cj], sposC); atomicAdd(&g_cpos[cj], cposC); }
                    if (hpC > -BIGF) atomicMax(&g_hp[cj], f2o(hpC));
                    atomicMin(&g_hn[cj], f2o(hnC));
                }
            }
        }
    }

    // row-side merge
    #pragma unroll
    for (int o=1; o<=2; o<<=1){
        #pragma unroll
        for (int x=0;x<4;x++){
            sume4[x] += __shfl_xor_sync(0xffffffffu, sume4[x], o);
            spos4[x] += __shfl_xor_sync(0xffffffffu, spos4[x], o);
            cpos4[x] += __shfl_xor_sync(0xffffffffu, cpos4[x], o);
            hp4[x] = fmaxf(hp4[x], __shfl_xor_sync(0xffffffffu, hp4[x], o));
            hn4[x] = fminf(hn4[x], __shfl_xor_sync(0xffffffffu, hn4[x], o));
        }
    }
    if ((lane&3)==0){
        #pragma unroll
        for (int x=0;x<4;x++){
            int ri = r4[x];
            atomicAdd(&g_sume[ri], sume4[x]);
            if (cpos4[x] > 0.f){ atomicAdd(&g_spos[ri], spos4[x]); atomicAdd(&g_cpos[ri], cpos4[x]); }
            if (hp4[x] > -BIGF) atomicMax(&g_hp[ri], f2o(hp4[x]));
            atomicMin(&g_hn[ri], f2o(hn4[x]));
        }
    }
}

// ---------------- classifier (BK=64) ----------------
__global__ __launch_bounds__(256,2) void cls_kernel(
    const float* __restrict__ bbias, const int* __restrict__ lab)
{
    extern __shared__ char smem[];
    uint32_t sb = (uint32_t)__cvta_generic_to_shared(smem);
    int tid = threadIdx.x, lane = tid&31, wid = tid>>5;
    int wm = wid&3, wn = wid>>2;
    int row0 = blockIdx.x*BM;
    int col0 = blockIdx.y*BM;
    float* s_b = (float*)(smem + NST*STG);
    if (tid < 128){
        int cj = col0 + tid;
        s_b[tid] = (cj < Cn) ? bbias[cj] : 0.f;
    }

    int rL = tid>>3, cL = tid&7;
    uint32_t dA = SW2(rL, cL);
    const __nv_bfloat16* gA = g_Fb + (size_t)(row0+rL)*Dn + cL*8;
    const __nv_bfloat16* gB = g_Wb + (size_t)(col0+rL)*Dn + cL*8;

    int q = lane>>3, rr = lane&7;
    int rowA[2], rowB[4];
    #pragma unroll
    for (int mt=0; mt<2; mt++) rowA[mt] = (wm*32 + mt*16 + rr + (q&1)*8)*128;
    #pragma unroll
    for (int nt4=0; nt4<4; nt4++) rowB[nt4] = 16384 + (wn*64 + nt4*16 + rr + (q>>1)*8)*128;
    int qhi = q>>1, qlo = q&1;

    float acc[2][8][4];
    #pragma unroll
    for (int i=0;i<2;i++)
        #pragma unroll
        for (int j=0;j<8;j++)
            #pragma unroll
            for (int e=0;e<4;e++) acc[i][j][e]=0.f;

    #define CLOAD(j, stq) do { \
        uint32_t _st = sb + (stq)*STG; \
        size_t _ko = (size_t)(j)*BK; \
        _Pragma("unroll") \
        for (int _i=0;_i<4;_i++){ \
            CP16(_st+dA+4096*_i,       gA + (size_t)(32*_i)*Dn + _ko); \
            CP16(_st+16384+dA+4096*_i, gB + (size_t)(32*_i)*Dn + _ko); \
        } \
    } while(0)

    CLOAD(0,0); CP_COMMIT();
    CLOAD(1,1); CP_COMMIT();

    int cs = 0, ls = 2;
    for (int j=0; j<KT; j++){
        CP_WAIT(1);
        __syncthreads();
        if (j+2 < KT){
            CLOAD(j+2, ls);
            ls++; if (ls==NST) ls=0;
        }
        CP_COMMIT();
        uint32_t st = sb + cs*STG;
        cs++; if (cs==NST) cs=0;
        #pragma unroll
        for (int ks=0; ks<4; ks++){
            uint32_t chA = st + ((((ks*2+qhi) ^ rr))<<4);
            uint32_t chB = st + ((((ks*2+qlo) ^ rr))<<4);
            uint32_t a[2][4], b[8][2];
            ldm4(a[0][0],a[0][1],a[0][2],a[0][3], chA + rowA[0]);
            ldm4(a[1][0],a[1][1],a[1][2],a[1][3], chA + rowA[1]);
            #pragma unroll
            for (int nt4=0; nt4<4; nt4++)
                ldm4(b[nt4*2][0],b[nt4*2][1],b[nt4*2+1][0],b[nt4*2+1][1], chB + rowB[nt4]);
            #pragma unroll
            for (int mt=0; mt<2; mt++)
                #pragma unroll
                for (int nt=0; nt<8; nt++)
                    mma16816(acc[mt][nt], a[mt], b[nt]);
        }
    }
    #undef CLOAD

    float se4[4];
    #pragma unroll
    for (int x=0;x<4;x++) se4[x]=0.f;
    #pragma unroll
    for (int mt=0; mt<2; mt++)
        #pragma unroll
        for (int h=0; h<2; h++){
            int x = mt*2 + h;
            int ri = row0 + wm*32 + mt*16 + h*8 + (lane>>2);
            int labi = lab[ri];
            #pragma unroll
            for (int nt=0; nt<8; nt++){
                int cl = wn*64 + nt*8 + (lane&3)*2;
                #pragma unroll
                for (int u=0; u<2; u++){
                    int clu = cl+u, cj = col0+clu;
                    float logit = acc[mt][nt][h*2+u] + s_b[clu];
                    if (cj < Cn){
                        se4[x] += __expf(logit);
                        if (cj == labi) g_lab_logit[ri] = logit;
                    }
                }
            }
        }
    #pragma unroll
    for (int o=1;o<=2;o<<=1)
        #pragma unroll
        for (int x=0;x<4;x++)
            se4[x] += __shfl_xor_sync(0xffffffffu, se4[x], o);
    if ((lane&3)==0){
        #pragma unroll
        for (int x=0;x<4;x++){
            int ri = row0 + wm*32 + (x>>1)*16 + (x&1)*8 + (lane>>2);
            atomicAdd(&g_sume_cls[ri], se4[x]);
        }
    }
}

// ---------------- final reductions ----------------
__global__ void fin1(){
    int i = blockIdx.x*blockDim.x + threadIdx.x;
    float tri=0.f, nv=0.f, stn=0.f, stc=0.f, cls=0.f;
    if (i < Bn){
        float lse = IT + logf(g_sume[i]);
        stn = g_spos[i] - g_cpos[i]*lse;
        stc = g_cpos[i];
        float hp = o2f(g_hp[i]), hn = o2f(g_hn[i]);
        bool valid = hp > -1.0e8f;
        tri = valid ? fmaxf(hp - hn + MARGINF, 0.f) : 0.f;
        nv  = valid ? 1.f : 0.f;
        cls = logf(g_sume_cls[i]) - g_lab_logit[i];
    }
    #pragma unroll
    for (int o=16;o;o>>=1){
        tri += __shfl_down_sync(0xffffffffu, tri, o);
        nv  += __shfl_down_sync(0xffffffffu, nv , o);
        stn += __shfl_down_sync(0xffffffffu, stn, o);
        stc += __shfl_down_sync(0xffffffffu, stc, o);
        cls += __shfl_down_sync(0xffffffffu, cls, o);
    }
    if ((threadIdx.x & 31) == 0){
        atomicAdd(&g_acc[0], tri);
        atomicAdd(&g_acc[1], nv);
        atomicAdd(&g_acc[2], stn);
        atomicAdd(&g_acc[3], stc);
        atomicAdd(&g_acc[4], cls);
    }
}
__global__ void fin2(float* out){
    float nv = g_acc[1], npos = g_acc[3];
    float loss_id  = g_acc[4] / (float)Bn;
    float loss_tri = (nv   > 0.f) ? g_acc[0] / fmaxf(nv,   1.f) : 0.f;
    float loss_st  = (npos > 0.f) ? (-g_acc[2]) / fmaxf(npos, 1.f) : 0.f;
    out[0] = loss_id + L_TRI*loss_tri + L_ST*loss_st;
}

// ---------------- launch ----------------
extern "C" void kernel_launch(void* const* d_in, const int* in_sizes, int n_in,
                              void* d_out, int out_size){
    const float* F     = (const float*)d_in[0];
    const int*   lab   = (const int*)  d_in[1];
    const int*   cam   = (const int*)  d_in[2];
    const float* ts    = (const float*)d_in[3];
    const float* reach = (const float*)d_in[4];
    const float* W     = (const float*)d_in[5];
    const float* bbias = (const float*)d_in[6];
    float* out = (float*)d_out;

    cudaFuncSetAttribute(pair_kernel, cudaFuncAttributeMaxDynamicSharedMemorySize, SMEM_PAIR);
    cudaFuncSetAttribute(cls_kernel,  cudaFuncAttributeMaxDynamicSharedMemorySize, SMEM_CLS);

    convert_F_kernel<<<(Bn*(size_t)Dn/8)/256, 256>>>(F);
    convert_W_kernel<<<((size_t)CnP*Dn/8)/256, 256>>>(W);
    norm_kernel<<<Bn/8, 256>>>();
    pair_kernel<<<NTILE, 256, SMEM_PAIR>>>(lab, cam, ts, reach);
    dim3 g2(Bn/BM, CnP/BM);
    cls_kernel<<<g2, 256, SMEM_CLS>>>(bbias, lab);
    fin1<<<Bn/256, 256>>>();
    fin2<<<1,1>>>(out);
}